// round 1
// baseline (speedup 1.0000x reference)
#include <cuda_runtime.h>
#include <cuda_bf16.h>
#include <cstdint>
#include <cstddef>

// ---------------- problem constants ----------------
#define BTOK 4096          // B*T tokens
#define HDIM 4096          // hidden
#define VDIM 32000         // vocab
#define NTIL 250           // VDIM / BN
#define SEQT 512           // T
#define NSEQ 8             // B
#define IGNORE_IDX (-100)

// ---------------- GEMM tiling ----------------
#define BM 128
#define BN 128
#define BK 32
#define LDSA 40            // BK + 8 pad (bank-conflict-free ldmatrix)

// ---------------- device scratch (static; no runtime alloc) ----------------
__device__ __align__(256) __nv_bfloat16 g_xb[2][(size_t)BTOK * HDIM];
__device__ __align__(256) __nv_bfloat16 g_wb[2][(size_t)VDIM * HDIM];
__device__ float g_plse[2][BTOK][NTIL];   // partial LSE per (model, token, vocab-tile)
__device__ float g_tgt[2][BTOK];          // exact fp32 target logits
__device__ float g_logp[2][BTOK];
__device__ int   g_tidx[BTOK];

// ---------------- small helpers ----------------
__device__ __forceinline__ uint32_t smem_u32(const void* p) {
    return (uint32_t)__cvta_generic_to_shared(p);
}
__device__ __forceinline__ void ldmx4(uint32_t* r, uint32_t addr) {
    asm volatile("ldmatrix.sync.aligned.m8n8.x4.shared.b16 {%0,%1,%2,%3}, [%4];\n"
                 : "=r"(r[0]), "=r"(r[1]), "=r"(r[2]), "=r"(r[3]) : "r"(addr));
}
__device__ __forceinline__ void mma16816(float* d, const uint32_t* a, uint32_t b0, uint32_t b1) {
    asm volatile("mma.sync.aligned.m16n8k16.row.col.f32.bf16.bf16.f32 "
                 "{%0,%1,%2,%3}, {%4,%5,%6,%7}, {%8,%9}, {%0,%1,%2,%3};\n"
                 : "+f"(d[0]), "+f"(d[1]), "+f"(d[2]), "+f"(d[3])
                 : "r"(a[0]), "r"(a[1]), "r"(a[2]), "r"(a[3]), "r"(b0), "r"(b1));
}
#define CPA16(dst, src) asm volatile("cp.async.cg.shared.global [%0], [%1], 16;\n" :: "r"(dst), "l"(src))
#define CP_COMMIT()     asm volatile("cp.async.commit_group;\n")
#define CP_WAIT1()      asm volatile("cp.async.wait_group 1;\n")
#define CP_WAIT0()      asm volatile("cp.async.wait_group 0;\n")

__device__ __forceinline__ uint32_t pack_bf2(float a, float b) {
    __nv_bfloat162 h = __floats2bfloat162_rn(a, b);
    return *reinterpret_cast<uint32_t*>(&h);
}

// ---------------- kernel 0: normalize targets (int32 or int64 on the wire) ----------------
__global__ void norm_targets_kernel(const void* traw) {
    __shared__ int notI64;
    const int* t32 = (const int*)traw;
    if (threadIdx.x == 0) notI64 = 0;
    __syncthreads();
    // If data were int64, every high word is 0 (tgt>=0) or -1 (tgt=-100).
    // Inspect only the first BTOK/2 logical int64 slots = BTOK int32s (safe for both layouts).
    for (int i = threadIdx.x; i < BTOK / 2; i += blockDim.x) {
        int hi = t32[2 * i + 1];
        if (hi != 0 && hi != -1) notI64 = 1;
    }
    __syncthreads();
    if (notI64) {
        for (int i = threadIdx.x; i < BTOK; i += blockDim.x) g_tidx[i] = t32[i];
    } else {
        const long long* t64 = (const long long*)traw;
        for (int i = threadIdx.x; i < BTOK; i += blockDim.x) g_tidx[i] = (int)t64[i];
    }
}

// ---------------- kernel 1: fp32 -> bf16 conversion ----------------
__global__ void convert_kernel(const float4* __restrict__ src, int model, int is_w) {
    size_t n4 = is_w ? ((size_t)VDIM * HDIM / 4) : ((size_t)BTOK * HDIM / 4);
    size_t i = (size_t)blockIdx.x * blockDim.x + threadIdx.x;
    if (i >= n4) return;
    float4 v = src[i];
    uint2 o = make_uint2(pack_bf2(v.x, v.y), pack_bf2(v.z, v.w));
    uint2* dst = is_w ? reinterpret_cast<uint2*>(g_wb[model])
                      : reinterpret_cast<uint2*>(g_xb[model]);
    dst[i] = o;
}

// ---------------- kernel 2: fused GEMM + per-tile logsumexp ----------------
// grid = (BTOK/BM, VDIM/BN, 2). blockIdx.x fastest => blocks of one vocab-tile
// run together; X (33MB bf16) stays L2 resident, W streams ~once from HBM.
__global__ void __launch_bounds__(256, 1)
gemm_lse_kernel(const float* __restrict__ bias0, const float* __restrict__ bias1) {
    const int mtile = blockIdx.x, ntile = blockIdx.y, model = blockIdx.z;
    const int m0 = mtile * BM, n0 = ntile * BN;
    const __nv_bfloat16* __restrict__ Ag = g_xb[model];
    const __nv_bfloat16* __restrict__ Bg = g_wb[model];
    const float* __restrict__ bias = model ? bias1 : bias0;

    __shared__ __nv_bfloat16 sA[2][BM][LDSA];
    __shared__ __nv_bfloat16 sB[2][BN][LDSA];
    __shared__ float sMax[BM][2], sSum[BM][2];

    const int tid = threadIdx.x;
    const int lane = tid & 31, warp = tid >> 5;
    const int wm = warp & 3, wn = warp >> 2;   // 4x2 warp grid, warp tile 32x64

    float acc[2][8][4];
#pragma unroll
    for (int i = 0; i < 2; i++)
#pragma unroll
        for (int j = 0; j < 8; j++)
#pragma unroll
            for (int c = 0; c < 4; c++) acc[i][j][c] = 0.f;

    auto issue_loads = [&](int buf, int k0) {
#pragma unroll
        for (int i = 0; i < 2; i++) {
            int task = tid + i * 256;
            int row = task >> 2, ch = task & 3;
            const __nv_bfloat16* srcA = Ag + (size_t)(m0 + row) * HDIM + k0 + ch * 8;
            CPA16(smem_u32(&sA[buf][row][ch * 8]), srcA);
            const __nv_bfloat16* srcB = Bg + (size_t)(n0 + row) * HDIM + k0 + ch * 8;
            CPA16(smem_u32(&sB[buf][row][ch * 8]), srcB);
        }
    };

    issue_loads(0, 0);
    CP_COMMIT();

    const int KT = HDIM / BK;   // 128
    for (int kt = 0; kt < KT; kt++) {
        int buf = kt & 1;
        if (kt + 1 < KT) {
            issue_loads(buf ^ 1, (kt + 1) * BK);
            CP_COMMIT();
            CP_WAIT1();
        } else {
            CP_WAIT0();
        }
        __syncthreads();
#pragma unroll
        for (int kk = 0; kk < 2; kk++) {
            uint32_t af[2][4];
#pragma unroll
            for (int mi = 0; mi < 2; mi++)
                ldmx4(af[mi], smem_u32(&sA[buf][wm * 32 + mi * 16 + (lane & 15)]
                                           [kk * 16 + (lane >> 4) * 8]));
            uint32_t bf[4][4];
#pragma unroll
            for (int nb = 0; nb < 4; nb++)
                ldmx4(bf[nb], smem_u32(&sB[buf][wn * 64 + nb * 16 + (lane & 15)]
                                           [kk * 16 + (lane >> 4) * 8]));
#pragma unroll
            for (int mi = 0; mi < 2; mi++)
#pragma unroll
                for (int nj = 0; nj < 8; nj++)
                    mma16816(acc[mi][nj], af[mi], bf[nj >> 1][nj & 1], bf[nj >> 1][2 + (nj & 1)]);
        }
        __syncthreads();
    }

    // ------ epilogue: + bias, then per-row (token) max & sum-exp over this 128-col slice ------
    const int qr = lane >> 2, qc = lane & 3;
#pragma unroll
    for (int nj = 0; nj < 8; nj++) {
        int col = n0 + wn * 64 + nj * 8 + qc * 2;
        float b0v = bias[col], b1v = bias[col + 1];
#pragma unroll
        for (int mi = 0; mi < 2; mi++) {
            acc[mi][nj][0] += b0v; acc[mi][nj][1] += b1v;
            acc[mi][nj][2] += b0v; acc[mi][nj][3] += b1v;
        }
    }
#pragma unroll
    for (int mi = 0; mi < 2; mi++) {
#pragma unroll
        for (int h = 0; h < 2; h++) {
            float m = -3.0e38f;
#pragma unroll
            for (int nj = 0; nj < 8; nj++)
                m = fmaxf(m, fmaxf(acc[mi][nj][h * 2], acc[mi][nj][h * 2 + 1]));
            m = fmaxf(m, __shfl_xor_sync(0xffffffffu, m, 1));
            m = fmaxf(m, __shfl_xor_sync(0xffffffffu, m, 2));
            float s = 0.f;
#pragma unroll
            for (int nj = 0; nj < 8; nj++) {
                s += expf(acc[mi][nj][h * 2] - m);
                s += expf(acc[mi][nj][h * 2 + 1] - m);
            }
            s += __shfl_xor_sync(0xffffffffu, s, 1);
            s += __shfl_xor_sync(0xffffffffu, s, 2);
            if (qc == 0) {
                int r = wm * 32 + mi * 16 + h * 8 + qr;
                sMax[r][wn] = m;
                sSum[r][wn] = s;
            }
        }
    }
    __syncthreads();
    if (tid < BM) {
        float ma = sMax[tid][0], mb = sMax[tid][1];
        float mm = fmaxf(ma, mb);
        float ss = sSum[tid][0] * expf(ma - mm) + sSum[tid][1] * expf(mb - mm);
        g_plse[model][m0 + tid][ntile] = mm + logf(ss);
    }
}

// ---------------- kernel 3: exact fp32 target logits (warp per (model, token)) ----------------
__global__ void tgt_kernel(const float* __restrict__ x0, const float* __restrict__ w0,
                           const float* __restrict__ b0, const float* __restrict__ x1,
                           const float* __restrict__ w1, const float* __restrict__ b1) {
    int gw = (int)((blockIdx.x * blockDim.x + threadIdx.x) >> 5);
    int lane = threadIdx.x & 31;
    if (gw >= 2 * BTOK) return;
    int model = gw >> 12, t = gw & (BTOK - 1);
    int tg = g_tidx[t];
    float r = 0.f;
    if (tg >= 0 && tg < VDIM) {
        const float4* x4 = (const float4*)((model ? x1 : x0) + (size_t)t * HDIM);
        const float4* w4 = (const float4*)((model ? w1 : w0) + (size_t)tg * HDIM);
        float s = 0.f;
        for (int k = lane; k < HDIM / 4; k += 32) {
            float4 a = x4[k], bb = w4[k];
            s = fmaf(a.x, bb.x, fmaf(a.y, bb.y, fmaf(a.z, bb.z, fmaf(a.w, bb.w, s))));
        }
#pragma unroll
        for (int o = 16; o; o >>= 1) s += __shfl_xor_sync(0xffffffffu, s, o);
        r = s + (model ? b1 : b0)[tg];
    }
    if (lane == 0) g_tgt[model][t] = r;
}

// ---------------- kernel 4: merge partial LSEs + token logp ----------------
__global__ void lse_kernel() {
    int gw = (int)((blockIdx.x * blockDim.x + threadIdx.x) >> 5);
    int lane = threadIdx.x & 31;
    if (gw >= 2 * BTOK) return;
    int model = gw >> 12, t = gw & (BTOK - 1);
    float m = -3.0e38f;
    for (int i = lane; i < NTIL; i += 32) m = fmaxf(m, g_plse[model][t][i]);
#pragma unroll
    for (int o = 16; o; o >>= 1) m = fmaxf(m, __shfl_xor_sync(0xffffffffu, m, o));
    float s = 0.f;
    for (int i = lane; i < NTIL; i += 32) s += expf(g_plse[model][t][i] - m);
#pragma unroll
    for (int o = 16; o; o >>= 1) s += __shfl_xor_sync(0xffffffffu, s, o);
    if (lane == 0) {
        int tg = g_tidx[t];
        g_logp[model][t] = (tg == IGNORE_IDX) ? 0.f : (g_tgt[model][t] - (m + logf(s)));
    }
}

// ---------------- kernel 5: sequence sums + DPO loss ----------------
__global__ void loss_kernel(float* __restrict__ out) {
    __shared__ double seq[16];   // [model*8 + s]
    int tid = threadIdx.x;
    if (tid < 16) {
        int model = tid >> 3, s = tid & 7;
        double a = 0.0;
        for (int t = 0; t < SEQT; t++) a += (double)g_logp[model][s * SEQT + t];
        seq[tid] = a;
    }
    __syncthreads();
    if (tid == 0) {
        double L = 0.0;
        for (int p = 0; p < 4; p++) {
            double c = seq[p], r = seq[4 + p];
            double rc = seq[8 + p], rr = seq[12 + p];
            double d = 0.1 * ((c - rc) - (r - rr));
            double nl = (d > 0.0) ? log1p(exp(-d)) : (-d + log1p(exp(d)));
            L += nl;
        }
        out[0] = (float)(L / 4.0);
    }
}

// ---------------- launch ----------------
extern "C" void kernel_launch(void* const* d_in, const int* in_sizes, int n_in,
                              void* d_out, int out_size) {
    const float* x  = (const float*)d_in[0];
    const float* w  = (const float*)d_in[1];
    const float* b  = (const float*)d_in[2];
    const float* rx = (const float*)d_in[3];
    const float* rw = (const float*)d_in[4];
    const float* rb = (const float*)d_in[5];
    const void*  tg = d_in[6];

    norm_targets_kernel<<<1, 256>>>(tg);

    unsigned gx = (unsigned)(((size_t)BTOK * HDIM / 4 + 255) / 256);
    unsigned gwv = (unsigned)(((size_t)VDIM * HDIM / 4 + 255) / 256);
    convert_kernel<<<gx, 256>>>((const float4*)x, 0, 0);
    convert_kernel<<<gx, 256>>>((const float4*)rx, 1, 0);
    convert_kernel<<<gwv, 256>>>((const float4*)w, 0, 1);
    convert_kernel<<<gwv, 256>>>((const float4*)rw, 1, 1);

    dim3 gg(BTOK / BM, VDIM / BN, 2);   // (32, 250, 2)
    gemm_lse_kernel<<<gg, 256>>>(b, rb);

    tgt_kernel<<<(2 * BTOK) / 8, 256>>>(x, w, b, rx, rw, rb);
    lse_kernel<<<(2 * BTOK) / 8, 256>>>();
    loss_kernel<<<1, 256>>>((float*)d_out);
}

// round 3
// speedup vs baseline: 1.4276x; 1.4276x over previous
#include <cuda_runtime.h>
#include <cuda_bf16.h>
#include <cstdint>
#include <cstddef>

// ---------------- problem constants ----------------
#define BTOK 4096
#define HDIM 4096
#define VDIM 32000
#define SEQT 512
#define IGNORE_IDX (-100)

// ---------------- FP8 GEMM tiling ----------------
#define BM 256
#define BN 128
#define BKB 64                   // K bytes (fp8 elems) per stage
#define NK (HDIM / BKB)          // 64 chunks
#define NSTAGE 3
#define ROWB 80                  // padded smem row bytes (conflict-free ldmatrix)
#define A_BYTES (BM * ROWB)      // 20480
#define STAGE_BYTES (A_BYTES + BN * ROWB)   // 30720
#define RED_OFF (NSTAGE * STAGE_BYTES)      // 92160
#define SMEM_GEMM (RED_OFF + 4096)          // + sMax/sSum 256x2 each
#define NTIL (VDIM / BN)         // 250
#define SCALE 64.0f
#define INVS (1.0f / 4096.0f)    // 1/(SCALE*SCALE)

// ---------------- device scratch ----------------
__device__ __align__(256) uint8_t g_xq[2][(size_t)BTOK * HDIM];
__device__ __align__(256) uint8_t g_wq[2][(size_t)VDIM * HDIM];
__device__ float g_plse[2][BTOK][NTIL];
__device__ float g_tgt[2][BTOK];
__device__ float g_logp[2][BTOK];
__device__ int   g_tidx[BTOK];

// ---------------- helpers ----------------
__device__ __forceinline__ uint32_t smem_u32(const void* p) {
    return (uint32_t)__cvta_generic_to_shared(p);
}
__device__ __forceinline__ void ldmx4(uint32_t* r, uint32_t addr) {
    asm volatile("ldmatrix.sync.aligned.m8n8.x4.shared.b16 {%0,%1,%2,%3}, [%4];\n"
                 : "=r"(r[0]), "=r"(r[1]), "=r"(r[2]), "=r"(r[3]) : "r"(addr));
}
__device__ __forceinline__ void mma_fp8(float* d, const uint32_t* a, uint32_t b0, uint32_t b1) {
    asm volatile("mma.sync.aligned.m16n8k32.row.col.f32.e4m3.e4m3.f32 "
                 "{%0,%1,%2,%3}, {%4,%5,%6,%7}, {%8,%9}, {%0,%1,%2,%3};\n"
                 : "+f"(d[0]), "+f"(d[1]), "+f"(d[2]), "+f"(d[3])
                 : "r"(a[0]), "r"(a[1]), "r"(a[2]), "r"(a[3]), "r"(b0), "r"(b1));
}
#define CPA16(dst, src) asm volatile("cp.async.cg.shared.global [%0], [%1], 16;" :: "r"(dst), "l"(src))
#define CP_COMMIT()     asm volatile("cp.async.commit_group;")
#define CP_WAIT1()      asm volatile("cp.async.wait_group 1;")
#define CP_WAIT0()      asm volatile("cp.async.wait_group 0;")

__device__ __forceinline__ uint32_t pack4_e4m3(float f0, float f1, float f2, float f3) {
    uint16_t lo, hi;
    asm("cvt.rn.satfinite.e4m3x2.f32 %0, %1, %2;" : "=h"(lo) : "f"(f1), "f"(f0));
    asm("cvt.rn.satfinite.e4m3x2.f32 %0, %1, %2;" : "=h"(hi) : "f"(f3), "f"(f2));
    return (uint32_t)lo | ((uint32_t)hi << 16);
}

// ---------------- kernel 0: normalize targets ----------------
__global__ void norm_targets_kernel(const void* traw) {
    __shared__ int notI64;
    const int* t32 = (const int*)traw;
    if (threadIdx.x == 0) notI64 = 0;
    __syncthreads();
    for (int i = threadIdx.x; i < BTOK / 2; i += blockDim.x) {
        int hi = t32[2 * i + 1];
        if (hi != 0 && hi != -1) notI64 = 1;
    }
    __syncthreads();
    if (notI64) {
        for (int i = threadIdx.x; i < BTOK; i += blockDim.x) g_tidx[i] = t32[i];
    } else {
        const long long* t64 = (const long long*)traw;
        for (int i = threadIdx.x; i < BTOK; i += blockDim.x) g_tidx[i] = (int)t64[i];
    }
}

// ---------------- kernel 1: fp32 -> scaled e4m3 ----------------
__global__ void convert_fp8_kernel(const float4* __restrict__ src, int model, int is_w) {
    size_t n4 = is_w ? ((size_t)VDIM * HDIM / 4) : ((size_t)BTOK * HDIM / 4);
    size_t i = (size_t)blockIdx.x * blockDim.x + threadIdx.x;
    if (i >= n4) return;
    float4 v = src[i];
    uint32_t* dst = is_w ? reinterpret_cast<uint32_t*>(g_wq[model])
                         : reinterpret_cast<uint32_t*>(g_xq[model]);
    dst[i] = pack4_e4m3(v.x * SCALE, v.y * SCALE, v.z * SCALE, v.w * SCALE);
}

// ---------------- kernel 2: FP8 GEMM (256x128 tile) + fused per-tile LSE ----------------
// 8 warps, warp tile 64x64. 3-stage cp.async pipeline, 1 barrier per K-chunk.
__global__ void __launch_bounds__(256, 1)
gemm_lse_kernel(const float* __restrict__ bias0, const float* __restrict__ bias1) {
    extern __shared__ char smem[];
    const uint32_t sb = smem_u32(smem);
    const int mtile = blockIdx.x, ntile = blockIdx.y, model = blockIdx.z;
    const uint8_t* __restrict__ Ab = g_xq[model] + (size_t)(mtile * BM) * HDIM;
    const uint8_t* __restrict__ Bb = g_wq[model] + (size_t)(ntile * BN) * HDIM;
    const float* __restrict__ bias = model ? bias1 : bias0;

    const int tid = threadIdx.x;
    const int lane = tid & 31, warp = tid >> 5;
    const int wm = warp & 3, wn = warp >> 2;

    float acc[4][8][4];
#pragma unroll
    for (int i = 0; i < 4; i++)
#pragma unroll
        for (int j = 0; j < 8; j++)
#pragma unroll
            for (int c = 0; c < 4; c++) acc[i][j][c] = 0.f;

    // per-thread cp.async tasks: 1536 x 16B (A:1024, B:512) -> 6 per thread
    auto issue = [&](int s, int kt) {
        const uint32_t stA = sb + s * STAGE_BYTES;
        const int k0 = kt * BKB;
#pragma unroll
        for (int i = 0; i < 6; i++) {
            int task = i * 256 + tid;
            if (task < 1024) {
                int row = task >> 2, ch = task & 3;
                CPA16(stA + row * ROWB + ch * 16,
                      Ab + (size_t)row * HDIM + k0 + ch * 16);
            } else {
                int t2 = task - 1024;
                int row = t2 >> 2, ch = t2 & 3;
                CPA16(stA + A_BYTES + row * ROWB + ch * 16,
                      Bb + (size_t)row * HDIM + k0 + ch * 16);
            }
        }
    };

    // precomputed ldmatrix lane offsets
    const uint32_t lrow = (uint32_t)(lane & 15) * ROWB;
    const uint32_t lcol = (uint32_t)(lane >> 4) * 16;

    issue(0, 0); CP_COMMIT();
    issue(1, 1); CP_COMMIT();

    for (int kt = 0; kt < NK; kt++) {
        if (kt == NK - 1) { CP_WAIT0(); } else { CP_WAIT1(); }
        __syncthreads();
        if (kt + 2 < NK) {
            int s = kt + 2; s -= (s >= NSTAGE) ? NSTAGE : 0; s -= (s >= NSTAGE) ? NSTAGE : 0;
            issue((kt + 2) % NSTAGE, kt + 2);
            CP_COMMIT();
        }
        const int st = kt % NSTAGE;
        const uint32_t aB = sb + st * STAGE_BYTES;
        const uint32_t bB = aB + A_BYTES;
#pragma unroll
        for (int kk = 0; kk < 2; kk++) {
            uint32_t af[4][4];
#pragma unroll
            for (int mi = 0; mi < 4; mi++)
                ldmx4(af[mi], aB + (uint32_t)(wm * 64 + mi * 16) * ROWB + lrow
                               + kk * 32 + lcol);
            uint32_t bfr[4][4];
#pragma unroll
            for (int nb = 0; nb < 4; nb++)
                ldmx4(bfr[nb], bB + (uint32_t)(wn * 64 + nb * 16) * ROWB + lrow
                                + kk * 32 + lcol);
#pragma unroll
            for (int mi = 0; mi < 4; mi++)
#pragma unroll
                for (int nj = 0; nj < 8; nj++)
                    mma_fp8(acc[mi][nj], af[mi],
                            bfr[nj >> 1][nj & 1], bfr[nj >> 1][2 + (nj & 1)]);
        }
    }

    // ---------------- epilogue: scale, + bias, per-row LSE over 128 cols ----------------
    const int qr = lane >> 2, qc = lane & 3;
    float bb[16];
#pragma unroll
    for (int nj = 0; nj < 8; nj++) {
        int col = ntile * BN + wn * 64 + nj * 8 + qc * 2;
        bb[2 * nj]     = __ldg(bias + col);
        bb[2 * nj + 1] = __ldg(bias + col + 1);
    }
#pragma unroll
    for (int mi = 0; mi < 4; mi++)
#pragma unroll
        for (int nj = 0; nj < 8; nj++)
#pragma unroll
            for (int c = 0; c < 4; c++)
                acc[mi][nj][c] = acc[mi][nj][c] * INVS + bb[2 * nj + (c & 1)];

    float* sMax = (float*)(smem + RED_OFF);          // [256][2]
    float* sSum = (float*)(smem + RED_OFF + 2048);   // [256][2]
#pragma unroll
    for (int mi = 0; mi < 4; mi++) {
#pragma unroll
        for (int h = 0; h < 2; h++) {
            float m = -3.0e38f;
#pragma unroll
            for (int nj = 0; nj < 8; nj++)
                m = fmaxf(m, fmaxf(acc[mi][nj][2 * h], acc[mi][nj][2 * h + 1]));
            m = fmaxf(m, __shfl_xor_sync(0xffffffffu, m, 1));
            m = fmaxf(m, __shfl_xor_sync(0xffffffffu, m, 2));
            float s = 0.f;
#pragma unroll
            for (int nj = 0; nj < 8; nj++) {
                s += __expf(acc[mi][nj][2 * h] - m);
                s += __expf(acc[mi][nj][2 * h + 1] - m);
            }
            s += __shfl_xor_sync(0xffffffffu, s, 1);
            s += __shfl_xor_sync(0xffffffffu, s, 2);
            if (qc == 0) {
                int r = wm * 64 + mi * 16 + h * 8 + qr;
                sMax[r * 2 + wn] = m;
                sSum[r * 2 + wn] = s;
            }
        }
    }
    __syncthreads();
    {
        float ma = sMax[tid * 2], mb = sMax[tid * 2 + 1];
        float mm = fmaxf(ma, mb);
        float ss = sSum[tid * 2] * __expf(ma - mm) + sSum[tid * 2 + 1] * __expf(mb - mm);
        g_plse[model][mtile * BM + tid][ntile] = mm + logf(ss);
    }
}

// ---------------- kernel 3: exact fp32 target logits ----------------
__global__ void tgt_kernel(const float* __restrict__ x0, const float* __restrict__ w0,
                           const float* __restrict__ b0, const float* __restrict__ x1,
                           const float* __restrict__ w1, const float* __restrict__ b1) {
    int gw = (int)((blockIdx.x * blockDim.x + threadIdx.x) >> 5);
    int lane = threadIdx.x & 31;
    if (gw >= 2 * BTOK) return;
    int model = gw >> 12, t = gw & (BTOK - 1);
    int tg = g_tidx[t];
    float r = 0.f;
    if (tg >= 0 && tg < VDIM) {
        const float4* x4 = (const float4*)((model ? x1 : x0) + (size_t)t * HDIM);
        const float4* w4 = (const float4*)((model ? w1 : w0) + (size_t)tg * HDIM);
        float s = 0.f;
        for (int k = lane; k < HDIM / 4; k += 32) {
            float4 a = x4[k], bbk = w4[k];
            s = fmaf(a.x, bbk.x, fmaf(a.y, bbk.y, fmaf(a.z, bbk.z, fmaf(a.w, bbk.w, s))));
        }
#pragma unroll
        for (int o = 16; o; o >>= 1) s += __shfl_xor_sync(0xffffffffu, s, o);
        r = s + (model ? b1 : b0)[tg];
    }
    if (lane == 0) g_tgt[model][t] = r;
}

// ---------------- kernel 4: merge partial LSEs ----------------
__global__ void lse_kernel() {
    int gw = (int)((blockIdx.x * blockDim.x + threadIdx.x) >> 5);
    int lane = threadIdx.x & 31;
    if (gw >= 2 * BTOK) return;
    int model = gw >> 12, t = gw & (BTOK - 1);
    float m = -3.0e38f;
    for (int i = lane; i < NTIL; i += 32) m = fmaxf(m, g_plse[model][t][i]);
#pragma unroll
    for (int o = 16; o; o >>= 1) m = fmaxf(m, __shfl_xor_sync(0xffffffffu, m, o));
    float s = 0.f;
    for (int i = lane; i < NTIL; i += 32) s += expf(g_plse[model][t][i] - m);
#pragma unroll
    for (int o = 16; o; o >>= 1) s += __shfl_xor_sync(0xffffffffu, s, o);
    if (lane == 0) {
        int tg = g_tidx[t];
        g_logp[model][t] = (tg == IGNORE_IDX) ? 0.f : (g_tgt[model][t] - (m + logf(s)));
    }
}

// ---------------- kernel 5: sequence sums + DPO loss ----------------
__global__ void loss_kernel(float* __restrict__ out) {
    __shared__ double seq[16];
    int tid = threadIdx.x;
    if (tid < 16) {
        int model = tid >> 3, s = tid & 7;
        double a = 0.0;
        for (int t = 0; t < SEQT; t++) a += (double)g_logp[model][s * SEQT + t];
        seq[tid] = a;
    }
    __syncthreads();
    if (tid == 0) {
        double L = 0.0;
        for (int p = 0; p < 4; p++) {
            double c = seq[p], r = seq[4 + p];
            double rc = seq[8 + p], rr = seq[12 + p];
            double d = 0.1 * ((c - rc) - (r - rr));
            double nl = (d > 0.0) ? log1p(exp(-d)) : (-d + log1p(exp(d)));
            L += nl;
        }
        out[0] = (float)(L / 4.0);
    }
}

// ---------------- launch ----------------
extern "C" void kernel_launch(void* const* d_in, const int* in_sizes, int n_in,
                              void* d_out, int out_size) {
    const float* x  = (const float*)d_in[0];
    const float* w  = (const float*)d_in[1];
    const float* b  = (const float*)d_in[2];
    const float* rx = (const float*)d_in[3];
    const float* rw = (const float*)d_in[4];
    const float* rb = (const float*)d_in[5];
    const void*  tg = d_in[6];

    norm_targets_kernel<<<1, 256>>>(tg);

    unsigned gx  = (unsigned)(((size_t)BTOK * HDIM / 4 + 255) / 256);
    unsigned gwv = (unsigned)(((size_t)VDIM * HDIM / 4 + 255) / 256);
    convert_fp8_kernel<<<gx, 256>>>((const float4*)x, 0, 0);
    convert_fp8_kernel<<<gx, 256>>>((const float4*)rx, 1, 0);
    convert_fp8_kernel<<<gwv, 256>>>((const float4*)w, 0, 1);
    convert_fp8_kernel<<<gwv, 256>>>((const float4*)rw, 1, 1);

    cudaFuncSetAttribute(gemm_lse_kernel,
                         cudaFuncAttributeMaxDynamicSharedMemorySize, SMEM_GEMM);
    dim3 gg(BTOK / BM, VDIM / BN, 2);   // (16, 250, 2), mtile fastest
    gemm_lse_kernel<<<gg, 256, SMEM_GEMM>>>(b, rb);

    tgt_kernel<<<(2 * BTOK) / 8, 256>>>(x, w, b, rx, rw, rb);
    lse_kernel<<<(2 * BTOK) / 8, 256>>>();
    loss_kernel<<<1, 256>>>((float*)d_out);
}

// round 4
// speedup vs baseline: 1.5265x; 1.0693x over previous
#include <cuda_runtime.h>
#include <cuda_bf16.h>
#include <cstdint>
#include <cstddef>

// ---------------- problem constants ----------------
#define BTOK 4096
#define HDIM 4096
#define VDIM 32000
#define SEQT 512
#define IGNORE_IDX (-100)

// ---------------- FP8 GEMM tiling ----------------
#define BM 256
#define BN 128
#define BKB 128                  // K bytes (fp8 elems) per stage = one 128B row
#define NK (HDIM / BKB)          // 32 chunks
#define NSTAGE 4
#define ROWB 128                 // smem row bytes, SW128 XOR swizzle
#define A_BYTES (BM * ROWB)      // 32768
#define STAGE_BYTES (A_BYTES + BN * ROWB)   // 49152
#define RED_OFF (NSTAGE * STAGE_BYTES)      // 196608
#define SMEM_GEMM (RED_OFF + 4096)
#define NTIL (VDIM / BN)         // 250
#define SCALE 64.0f
#define INVS (1.0f / 4096.0f)

#define SWZ(o) ((o) ^ (((o) >> 3) & 0x70))

// ---------------- device scratch ----------------
__device__ __align__(256) uint8_t g_xq[2][(size_t)BTOK * HDIM];
__device__ __align__(256) uint8_t g_wq[2][(size_t)VDIM * HDIM];
__device__ float g_plse[2][BTOK][NTIL];
__device__ float g_tgt[2][BTOK];
__device__ float g_logp[2][BTOK];
__device__ int   g_tidx[BTOK];

// ---------------- helpers ----------------
__device__ __forceinline__ uint32_t smem_u32(const void* p) {
    return (uint32_t)__cvta_generic_to_shared(p);
}
__device__ __forceinline__ void ldmx4(uint32_t* r, uint32_t addr) {
    asm volatile("ldmatrix.sync.aligned.m8n8.x4.shared.b16 {%0,%1,%2,%3}, [%4];\n"
                 : "=r"(r[0]), "=r"(r[1]), "=r"(r[2]), "=r"(r[3]) : "r"(addr));
}
__device__ __forceinline__ void mma_fp8(float* d, const uint32_t* a, uint32_t b0, uint32_t b1) {
    asm volatile("mma.sync.aligned.m16n8k32.row.col.f32.e4m3.e4m3.f32 "
                 "{%0,%1,%2,%3}, {%4,%5,%6,%7}, {%8,%9}, {%0,%1,%2,%3};\n"
                 : "+f"(d[0]), "+f"(d[1]), "+f"(d[2]), "+f"(d[3])
                 : "r"(a[0]), "r"(a[1]), "r"(a[2]), "r"(a[3]), "r"(b0), "r"(b1));
}
#define CPA16(dst, src) asm volatile("cp.async.cg.shared.global [%0], [%1], 16;" :: "r"(dst), "l"(src))
#define CP_COMMIT()     asm volatile("cp.async.commit_group;")
#define CP_WAIT2()      asm volatile("cp.async.wait_group 2;")
#define CP_WAIT1()      asm volatile("cp.async.wait_group 1;")
#define CP_WAIT0()      asm volatile("cp.async.wait_group 0;")

__device__ __forceinline__ uint32_t pack4_e4m3(float f0, float f1, float f2, float f3) {
    uint16_t lo, hi;
    asm("cvt.rn.satfinite.e4m3x2.f32 %0, %1, %2;" : "=h"(lo) : "f"(f1), "f"(f0));
    asm("cvt.rn.satfinite.e4m3x2.f32 %0, %1, %2;" : "=h"(hi) : "f"(f3), "f"(f2));
    return (uint32_t)lo | ((uint32_t)hi << 16);
}

// ---------------- kernel 0: normalize targets ----------------
__global__ void norm_targets_kernel(const void* traw) {
    __shared__ int notI64;
    const int* t32 = (const int*)traw;
    if (threadIdx.x == 0) notI64 = 0;
    __syncthreads();
    for (int i = threadIdx.x; i < BTOK / 2; i += blockDim.x) {
        int hi = t32[2 * i + 1];
        if (hi != 0 && hi != -1) notI64 = 1;
    }
    __syncthreads();
    if (notI64) {
        for (int i = threadIdx.x; i < BTOK; i += blockDim.x) g_tidx[i] = t32[i];
    } else {
        const long long* t64 = (const long long*)traw;
        for (int i = threadIdx.x; i < BTOK; i += blockDim.x) g_tidx[i] = (int)t64[i];
    }
}

// ---------------- kernel 1: fp32 -> scaled e4m3 ----------------
__global__ void convert_fp8_kernel(const float4* __restrict__ src, int model, int is_w) {
    size_t n4 = is_w ? ((size_t)VDIM * HDIM / 4) : ((size_t)BTOK * HDIM / 4);
    size_t i = (size_t)blockIdx.x * blockDim.x + threadIdx.x;
    if (i >= n4) return;
    float4 v = src[i];
    uint32_t* dst = is_w ? reinterpret_cast<uint32_t*>(g_wq[model])
                         : reinterpret_cast<uint32_t*>(g_xq[model]);
    dst[i] = pack4_e4m3(v.x * SCALE, v.y * SCALE, v.z * SCALE, v.w * SCALE);
}

// ---------------- kernel 2: FP8 GEMM (256x128 tile, SW128 swizzle) + fused LSE ------
// 8 warps, warp tile 64x64. 4-stage cp.async pipeline, 1 barrier per 128B K-chunk.
__global__ void __launch_bounds__(256, 1)
gemm_lse_kernel(const float* __restrict__ bias0, const float* __restrict__ bias1) {
    extern __shared__ char smem[];
    const uint32_t sb = smem_u32(smem);
    const int mtile = blockIdx.x, ntile = blockIdx.y, model = blockIdx.z;
    const uint8_t* __restrict__ Ab = g_xq[model] + (size_t)(mtile * BM) * HDIM;
    const uint8_t* __restrict__ Bb = g_wq[model] + (size_t)(ntile * BN) * HDIM;
    const float* __restrict__ bias = model ? bias1 : bias0;

    const int tid = threadIdx.x;
    const int lane = tid & 31, warp = tid >> 5;
    const int wm = warp & 3, wn = warp >> 2;

    float acc[4][8][4];
#pragma unroll
    for (int i = 0; i < 4; i++)
#pragma unroll
        for (int j = 0; j < 8; j++)
#pragma unroll
            for (int c = 0; c < 4; c++) acc[i][j][c] = 0.f;

    // cp.async: 3072 x 16B granules (A:2048, B:1024) -> 12 per thread, swizzled dst
    auto issue = [&](int s, int kt) {
        const uint32_t stA = sb + s * STAGE_BYTES;
        const int k0 = kt * BKB;
#pragma unroll
        for (int i = 0; i < 12; i++) {
            int task = i * 256 + tid;
            if (task < 2048) {
                int row = task >> 3, ch = task & 7;
                uint32_t rel = (uint32_t)(row * ROWB + ch * 16);
                CPA16(stA + SWZ(rel), Ab + (size_t)row * HDIM + k0 + ch * 16);
            } else {
                int t2 = task - 2048;
                int row = t2 >> 3, ch = t2 & 7;
                uint32_t rel = (uint32_t)(row * ROWB + ch * 16);
                CPA16(stA + A_BYTES + SWZ(rel), Bb + (size_t)row * HDIM + k0 + ch * 16);
            }
        }
    };

    const uint32_t lr = (uint32_t)(lane & 15);       // fragment row within 16-row group
    const uint32_t lc16 = (uint32_t)(lane >> 4) * 16;

    issue(0, 0); CP_COMMIT();
    issue(1, 1); CP_COMMIT();
    issue(2, 2); CP_COMMIT();

    for (int kt = 0; kt < NK; kt++) {
        if (kt < NK - 2)      { CP_WAIT2(); }
        else if (kt == NK - 2){ CP_WAIT1(); }
        else                  { CP_WAIT0(); }
        __syncthreads();
        if (kt + 3 < NK) { issue((kt + 3) & (NSTAGE - 1), kt + 3); CP_COMMIT(); }

        const uint32_t aB = sb + (kt & (NSTAGE - 1)) * STAGE_BYTES;
        const uint32_t bB = aB + A_BYTES;
#pragma unroll
        for (int kk = 0; kk < 4; kk++) {
            const uint32_t cb = kk * 32 + lc16;
            uint32_t af[4][4];
#pragma unroll
            for (int mi = 0; mi < 4; mi++) {
                uint32_t rel = (uint32_t)(wm * 64 + mi * 16 + lr) * ROWB + cb;
                ldmx4(af[mi], aB + SWZ(rel));
            }
            uint32_t bfr[4][4];
#pragma unroll
            for (int nb = 0; nb < 4; nb++) {
                uint32_t rel = (uint32_t)(wn * 64 + nb * 16 + lr) * ROWB + cb;
                ldmx4(bfr[nb], bB + SWZ(rel));
            }
#pragma unroll
            for (int mi = 0; mi < 4; mi++)
#pragma unroll
                for (int nj = 0; nj < 8; nj++)
                    mma_fp8(acc[mi][nj], af[mi],
                            bfr[nj >> 1][nj & 1], bfr[nj >> 1][2 + (nj & 1)]);
        }
    }

    // ---------------- epilogue: scale, + bias, per-row LSE over 128 cols ----------------
    const int qr = lane >> 2, qc = lane & 3;
    float bb[16];
#pragma unroll
    for (int nj = 0; nj < 8; nj++) {
        int col = ntile * BN + wn * 64 + nj * 8 + qc * 2;
        bb[2 * nj]     = __ldg(bias + col);
        bb[2 * nj + 1] = __ldg(bias + col + 1);
    }
#pragma unroll
    for (int mi = 0; mi < 4; mi++)
#pragma unroll
        for (int nj = 0; nj < 8; nj++)
#pragma unroll
            for (int c = 0; c < 4; c++)
                acc[mi][nj][c] = acc[mi][nj][c] * INVS + bb[2 * nj + (c & 1)];

    float* sMax = (float*)(smem + RED_OFF);          // [256][2]
    float* sSum = (float*)(smem + RED_OFF + 2048);   // [256][2]
#pragma unroll
    for (int mi = 0; mi < 4; mi++) {
#pragma unroll
        for (int h = 0; h < 2; h++) {
            float m = -3.0e38f;
#pragma unroll
            for (int nj = 0; nj < 8; nj++)
                m = fmaxf(m, fmaxf(acc[mi][nj][2 * h], acc[mi][nj][2 * h + 1]));
            m = fmaxf(m, __shfl_xor_sync(0xffffffffu, m, 1));
            m = fmaxf(m, __shfl_xor_sync(0xffffffffu, m, 2));
            float s = 0.f;
#pragma unroll
            for (int nj = 0; nj < 8; nj++) {
                s += __expf(acc[mi][nj][2 * h] - m);
                s += __expf(acc[mi][nj][2 * h + 1] - m);
            }
            s += __shfl_xor_sync(0xffffffffu, s, 1);
            s += __shfl_xor_sync(0xffffffffu, s, 2);
            if (qc == 0) {
                int r = wm * 64 + mi * 16 + h * 8 + qr;
                sMax[r * 2 + wn] = m;
                sSum[r * 2 + wn] = s;
            }
        }
    }
    __syncthreads();
    {
        float ma = sMax[tid * 2], mb = sMax[tid * 2 + 1];
        float mm = fmaxf(ma, mb);
        float ss = sSum[tid * 2] * __expf(ma - mm) + sSum[tid * 2 + 1] * __expf(mb - mm);
        g_plse[model][mtile * BM + tid][ntile] = mm + logf(ss);
    }
}

// ---------------- kernel 3: exact fp32 target logits ----------------
__global__ void tgt_kernel(const float* __restrict__ x0, const float* __restrict__ w0,
                           const float* __restrict__ b0, const float* __restrict__ x1,
                           const float* __restrict__ w1, const float* __restrict__ b1) {
    int gw = (int)((blockIdx.x * blockDim.x + threadIdx.x) >> 5);
    int lane = threadIdx.x & 31;
    if (gw >= 2 * BTOK) return;
    int model = gw >> 12, t = gw & (BTOK - 1);
    int tg = g_tidx[t];
    float r = 0.f;
    if (tg >= 0 && tg < VDIM) {
        const float4* x4 = (const float4*)((model ? x1 : x0) + (size_t)t * HDIM);
        const float4* w4 = (const float4*)((model ? w1 : w0) + (size_t)tg * HDIM);
        float s = 0.f;
        for (int k = lane; k < HDIM / 4; k += 32) {
            float4 a = x4[k], bbk = w4[k];
            s = fmaf(a.x, bbk.x, fmaf(a.y, bbk.y, fmaf(a.z, bbk.z, fmaf(a.w, bbk.w, s))));
        }
#pragma unroll
        for (int o = 16; o; o >>= 1) s += __shfl_xor_sync(0xffffffffu, s, o);
        r = s + (model ? b1 : b0)[tg];
    }
    if (lane == 0) g_tgt[model][t] = r;
}

// ---------------- kernel 4: merge partial LSEs ----------------
__global__ void lse_kernel() {
    int gw = (int)((blockIdx.x * blockDim.x + threadIdx.x) >> 5);
    int lane = threadIdx.x & 31;
    if (gw >= 2 * BTOK) return;
    int model = gw >> 12, t = gw & (BTOK - 1);
    float m = -3.0e38f;
    for (int i = lane; i < NTIL; i += 32) m = fmaxf(m, g_plse[model][t][i]);
#pragma unroll
    for (int o = 16; o; o >>= 1) m = fmaxf(m, __shfl_xor_sync(0xffffffffu, m, o));
    float s = 0.f;
    for (int i = lane; i < NTIL; i += 32) s += expf(g_plse[model][t][i] - m);
#pragma unroll
    for (int o = 16; o; o >>= 1) s += __shfl_xor_sync(0xffffffffu, s, o);
    if (lane == 0) {
        int tg = g_tidx[t];
        g_logp[model][t] = (tg == IGNORE_IDX) ? 0.f : (g_tgt[model][t] - (m + logf(s)));
    }
}

// ---------------- kernel 5: sequence sums + DPO loss ----------------
__global__ void loss_kernel(float* __restrict__ out) {
    __shared__ double seq[16];
    int tid = threadIdx.x;
    if (tid < 16) {
        int model = tid >> 3, s = tid & 7;
        double a = 0.0;
        for (int t = 0; t < SEQT; t++) a += (double)g_logp[model][s * SEQT + t];
        seq[tid] = a;
    }
    __syncthreads();
    if (tid == 0) {
        double L = 0.0;
        for (int p = 0; p < 4; p++) {
            double c = seq[p], r = seq[4 + p];
            double rc = seq[8 + p], rr = seq[12 + p];
            double d = 0.1 * ((c - rc) - (r - rr));
            double nl = (d > 0.0) ? log1p(exp(-d)) : (-d + log1p(exp(d)));
            L += nl;
        }
        out[0] = (float)(L / 4.0);
    }
}

// ---------------- launch ----------------
extern "C" void kernel_launch(void* const* d_in, const int* in_sizes, int n_in,
                              void* d_out, int out_size) {
    const float* x  = (const float*)d_in[0];
    const float* w  = (const float*)d_in[1];
    const float* b  = (const float*)d_in[2];
    const float* rx = (const float*)d_in[3];
    const float* rw = (const float*)d_in[4];
    const float* rb = (const float*)d_in[5];
    const void*  tg = d_in[6];

    norm_targets_kernel<<<1, 256>>>(tg);

    unsigned gx  = (unsigned)(((size_t)BTOK * HDIM / 4 + 255) / 256);
    unsigned gwv = (unsigned)(((size_t)VDIM * HDIM / 4 + 255) / 256);
    convert_fp8_kernel<<<gx, 256>>>((const float4*)x, 0, 0);
    convert_fp8_kernel<<<gx, 256>>>((const float4*)rx, 1, 0);
    convert_fp8_kernel<<<gwv, 256>>>((const float4*)w, 0, 1);
    convert_fp8_kernel<<<gwv, 256>>>((const float4*)rw, 1, 1);

    cudaFuncSetAttribute(gemm_lse_kernel,
                         cudaFuncAttributeMaxDynamicSharedMemorySize, SMEM_GEMM);
    dim3 gg(BTOK / BM, VDIM / BN, 2);   // (16, 250, 2), mtile fastest
    gemm_lse_kernel<<<gg, 256, SMEM_GEMM>>>(b, rb);

    tgt_kernel<<<(2 * BTOK) / 8, 256>>>(x, w, b, rx, rw, rb);
    lse_kernel<<<(2 * BTOK) / 8, 256>>>();
    loss_kernel<<<1, 256>>>((float*)d_out);
}